// round 15
// baseline (speedup 1.0000x reference)
#include <cuda_runtime.h>
#include <cuda_bf16.h>
#include <cstdint>

#define DF 128          // feature dim
#define DH 512          // hidden dim
#define MAXN 10000      // nodes
#define MAXG 128        // >= n_graphs (100)
#define EPW 32          // edges per warp strip (R8 known-good)

// ---------------- static device scratch (no allocations allowed) ------------
__device__ __nv_bfloat16 g_nAh[MAXN * DF], g_nAl[MAXN * DF]; // nodes hi/lo
__device__ __nv_bfloat16 g_W1h[DH * DF],  g_W1l[DH * DF];    // W1^T [512x128]
__device__ __nv_bfloat16 g_W2h[DF * DH],  g_W2l[DF * DH];    // W2^T [128x512]
__device__ __nv_bfloat16 g_th[MAXN * DH], g_tl[MAXN * DH];   // relu layer hi/lo
__device__ float         g_h[MAXN * DF];                     // final h (fp32)
__device__ __nv_bfloat16 g_hb[MAXN * DF];                    // bf16 mirror (=hi)
__device__ float g_wsum[MAXG];
__device__ float g_esum[MAXG];
__device__ int   g_eoff[MAXG + 1];
__device__ int   g_nid[MAXG];

__device__ __forceinline__ uint32_t smem_u32(const void* p) {
    uint32_t a;
    asm("{ .reg .u64 t; cvta.to.shared.u64 t, %1; cvt.u32.u64 %0, t; }"
        : "=r"(a) : "l"(p));
    return a;
}
#define SW128(x) ((x) ^ (((x) >> 3) & 0x70))

__device__ __forceinline__ void ldsm_x4(uint32_t& r0, uint32_t& r1,
                                        uint32_t& r2, uint32_t& r3, uint32_t a) {
    asm volatile("ldmatrix.sync.aligned.m8n8.x4.shared.b16 {%0,%1,%2,%3}, [%4];"
                 : "=r"(r0), "=r"(r1), "=r"(r2), "=r"(r3) : "r"(a));
}
__device__ __forceinline__ void mma_bf16(float* d, const uint32_t* a,
                                         const uint32_t* b) {
    asm volatile(
        "mma.sync.aligned.m16n8k16.row.col.f32.bf16.bf16.f32 "
        "{%0,%1,%2,%3}, {%4,%5,%6,%7}, {%8,%9}, {%0,%1,%2,%3};"
        : "+f"(d[0]), "+f"(d[1]), "+f"(d[2]), "+f"(d[3])
        : "r"(a[0]), "r"(a[1]), "r"(a[2]), "r"(a[3]), "r"(b[0]), "r"(b[1]));
}

// ============================================================================
// Kernel 0: prefix sums + zero accumulators (runs every replay)
// ============================================================================
__global__ void prefix_kernel(const int* __restrict__ n_node,
                              const int* __restrict__ n_edge, int G) {
    int t = threadIdx.x;
    if (t < MAXG) { g_wsum[t] = 0.f; g_esum[t] = 0.f; }
    if (t == 0) {
        int ea = 0, na = 0;
        g_eoff[0] = 0;
        for (int g = 0; g < G; g++) {
            ea += n_edge[g]; g_eoff[g + 1] = ea;
            na += n_node[g]; g_nid[g] = na - 1;
        }
    }
}

// ============================================================================
// Split fp32 -> bf16 hi/lo (same layout)
// ============================================================================
__global__ void split_kernel(const float* __restrict__ in,
                             __nv_bfloat16* __restrict__ hi,
                             __nv_bfloat16* __restrict__ lo, int n) {
    int i = blockIdx.x * 256 + threadIdx.x;
    if (i < n) {
        float a = in[i];
        __nv_bfloat16 h = __float2bfloat16(a);
        hi[i] = h;
        lo[i] = __float2bfloat16(a - __bfloat162float(h));
    }
}

// ============================================================================
// Transpose + split: W [Kd x Nd] fp32 row-major -> T hi/lo [Nd x Kd] bf16
// ============================================================================
__global__ void tsplit_kernel(const float* __restrict__ W,
                              __nv_bfloat16* __restrict__ Th,
                              __nv_bfloat16* __restrict__ Tl, int Kd, int Nd) {
    int i = blockIdx.x * 256 + threadIdx.x;
    if (i < Kd * Nd) {
        int k = i / Nd, n = i % Nd;
        float a = W[i];
        __nv_bfloat16 h = __float2bfloat16(a);
        Th[(size_t)n * Kd + k] = h;
        Tl[(size_t)n * Kd + k] = __float2bfloat16(a - __bfloat162float(h));
    }
}

// ============================================================================
// bf16 mma.sync GEMM, 3-pass hi/lo: D = (Ah+Al) @ (Bh+Bl)^T  (hh, h*lo, lo*h)
// A [M x K] row-major bf16; B [N x K] row-major bf16 (i.e. W transposed).
// CTA: 128x128 tile, 256 threads = 8 warps in 4(m) x 2(n); warp tile 32x64.
// BK=64 (128B rows, SW128). Epilogue: +bias, relu; writes fp32 / bf16 hi/lo.
// ============================================================================
__global__ __launch_bounds__(256)
void gemm_mma(const __nv_bfloat16* __restrict__ Ah, const __nv_bfloat16* __restrict__ Al,
              const __nv_bfloat16* __restrict__ Bh, const __nv_bfloat16* __restrict__ Bl,
              const float* __restrict__ bias, float* __restrict__ Cf,
              __nv_bfloat16* __restrict__ Chi, __nv_bfloat16* __restrict__ Clo,
              int M, int N, int K, int doRelu) {
    __shared__ __align__(1024) uint8_t sA[128 * 128];  // 128 rows x 64 bf16
    __shared__ __align__(1024) uint8_t sB[128 * 128];

    int tid = threadIdx.x, lane = tid & 31, wid = tid >> 5;
    int warp_m = wid & 3;          // 4 m-slices of 32 rows
    int warp_n = wid >> 2;         // 2 n-slices of 64 cols
    int row0 = blockIdx.y * 128, col0 = blockIdx.x * 128;
    uint32_t sAa = smem_u32(sA), sBa = smem_u32(sB);
    int r8 = lane & 7, sel = lane >> 3;

    float acc[2][8][4];
    #pragma unroll
    for (int i = 0; i < 2; i++)
        #pragma unroll
        for (int j = 0; j < 8; j++)
            #pragma unroll
            for (int q = 0; q < 4; q++) acc[i][j][q] = 0.f;

    #pragma unroll 1
    for (int pass = 0; pass < 3; pass++) {
        const __nv_bfloat16* As = (pass == 2) ? Al : Ah;
        const __nv_bfloat16* Bs = (pass == 1) ? Bl : Bh;
        #pragma unroll 1
        for (int k0 = 0; k0 < K; k0 += 64) {
            // fill A tile (zero-pad OOB rows)
            for (int i = tid; i < 128 * 8; i += 256) {
                int r = i >> 3, c = i & 7;
                uint4 v = make_uint4(0, 0, 0, 0);
                int gr = row0 + r;
                if (gr < M) v = *(const uint4*)(As + (size_t)gr * K + k0 + c * 8);
                *(uint4*)(sA + SW128(r * 128 + c * 16)) = v;
            }
            // fill B tile (N is multiple of 128 in both GEMMs)
            for (int i = tid; i < 128 * 8; i += 256) {
                int r = i >> 3, c = i & 7;
                uint4 v = *(const uint4*)(Bs + (size_t)(col0 + r) * K + k0 + c * 8);
                *(uint4*)(sB + SW128(r * 128 + c * 16)) = v;
            }
            __syncthreads();

            #pragma unroll
            for (int kk = 0; kk < 4; kk++) {     // 4 x k16
                int kb = kk * 32;
                uint32_t a[2][4], b[8][2];
                #pragma unroll
                for (int mi = 0; mi < 2; mi++) {
                    // mats: (m+0,k+0B),(m+8,k+0B),(m+0,k+16B),(m+8,k+16B)
                    int mr = warp_m * 32 + mi * 16 + (sel & 1) * 8 + r8;
                    uint32_t ad = sAa + SW128(mr * 128 + kb + (sel >> 1) * 16);
                    ldsm_x4(a[mi][0], a[mi][1], a[mi][2], a[mi][3], ad);
                }
                #pragma unroll
                for (int nj = 0; nj < 4; nj++) {
                    // mats: (n+0,k+0B),(n+0,k+16B),(n+8,k+0B),(n+8,k+16B)
                    int nr = warp_n * 64 + nj * 16 + (sel >> 1) * 8 + r8;
                    uint32_t bd = sBa + SW128(nr * 128 + kb + (sel & 1) * 16);
                    ldsm_x4(b[nj * 2][0], b[nj * 2][1],
                            b[nj * 2 + 1][0], b[nj * 2 + 1][1], bd);
                }
                #pragma unroll
                for (int mi = 0; mi < 2; mi++)
                    #pragma unroll
                    for (int ni = 0; ni < 8; ni++)
                        mma_bf16(acc[mi][ni], a[mi], b[ni]);
            }
            __syncthreads();
        }
    }

    // ---- epilogue: frag (t/4, 2*(t&3)) rows/cols; bias + relu; stores ----
    int tr = lane >> 2, tc = (lane & 3) * 2;
    #pragma unroll
    for (int mi = 0; mi < 2; mi++) {
        int ra = row0 + warp_m * 32 + mi * 16 + tr;
        int rb = ra + 8;
        #pragma unroll
        for (int ni = 0; ni < 8; ni++) {
            int col = col0 + warp_n * 64 + ni * 8 + tc;
            float bb0 = __ldg(bias + col), bb1 = __ldg(bias + col + 1);
            float v0 = acc[mi][ni][0] + bb0, v1 = acc[mi][ni][1] + bb1;
            float v2 = acc[mi][ni][2] + bb0, v3 = acc[mi][ni][3] + bb1;
            if (doRelu) {
                v0 = fmaxf(v0, 0.f); v1 = fmaxf(v1, 0.f);
                v2 = fmaxf(v2, 0.f); v3 = fmaxf(v3, 0.f);
            }
            if (ra < M) {
                size_t o = (size_t)ra * N + col;
                if (Cf) *(float2*)(Cf + o) = make_float2(v0, v1);
                __nv_bfloat162 h2 = __floats2bfloat162_rn(v0, v1);
                *(unsigned*)(Chi + o) = *(unsigned*)&h2;
                if (Clo) {
                    __nv_bfloat162 l2 = __floats2bfloat162_rn(
                        v0 - __bfloat162float(h2.x), v1 - __bfloat162float(h2.y));
                    *(unsigned*)(Clo + o) = *(unsigned*)&l2;
                }
            }
            if (rb < M) {
                size_t o = (size_t)rb * N + col;
                if (Cf) *(float2*)(Cf + o) = make_float2(v2, v3);
                __nv_bfloat162 h2 = __floats2bfloat162_rn(v2, v3);
                *(unsigned*)(Chi + o) = *(unsigned*)&h2;
                if (Clo) {
                    __nv_bfloat162 l2 = __floats2bfloat162_rn(
                        v2 - __bfloat162float(h2.x), v3 - __bfloat162float(h2.y));
                    *(unsigned*)(Clo + o) = *(unsigned*)&l2;
                }
            }
        }
    }
}

// ============================================================================
// Edge kernel (R8 known-good, 40us): one warp per strip of EPW edges.
// ============================================================================
__global__ __launch_bounds__(256)
void edge_kernel(const float* __restrict__ ew,
                 const int* __restrict__ snd, const int* __restrict__ rcv,
                 int E, int G) {
    int lane = threadIdx.x & 31;
    int wl = threadIdx.x >> 5;
    int warp = blockIdx.x * 8 + wl;
    int base = warp * EPW;
    if (base >= E) return;
    int end = min(base + EPW, E);

    int lo = 0, hi = G;
    while (hi - lo > 1) {
        int mid = (lo + hi) >> 1;
        if (g_eoff[mid] <= base) lo = mid; else hi = mid;
    }
    int gid = lo;
    int bnd = g_eoff[gid + 1];

    const __nv_bfloat16* __restrict__ hb = g_hb;
    float acc = 0.f, wacc = 0.f;
    int e = base;
    for (;;) {
        int seg = min(end, bnd);
        #pragma unroll 4
        for (; e < seg; e++) {
            int s = __ldg(snd + e);
            int r = __ldg(rcv + e);
            float w = __ldg(ew + e);
            uint2 av = *(const uint2*)(hb + (size_t)s * DF + lane * 4);
            uint2 bv = *(const uint2*)(hb + (size_t)r * DF + lane * 4);
            unsigned d0, d1;
            asm("sub.rn.bf16x2 %0, %1, %2;" : "=r"(d0) : "r"(av.x), "r"(bv.x));
            asm("sub.rn.bf16x2 %0, %1, %2;" : "=r"(d1) : "r"(av.y), "r"(bv.y));
            float f0 = __uint_as_float(d0 << 16);
            float f1 = __uint_as_float(d0 & 0xFFFF0000u);
            float f2 = __uint_as_float(d1 << 16);
            float f3 = __uint_as_float(d1 & 0xFFFF0000u);
            float t = f0 * f0;
            t = fmaf(f1, f1, t);
            t = fmaf(f2, f2, t);
            t = fmaf(f3, f3, t);
            acc = fmaf(w, t, acc);
            if (lane == 0) wacc += w;
        }
        float v = acc;
        #pragma unroll
        for (int off = 16; off; off >>= 1)
            v += __shfl_xor_sync(0xffffffffu, v, off);
        if (lane == 0) {
            atomicAdd(&g_esum[gid], v);
            atomicAdd(&g_wsum[gid], wacc);
        }
        if (e >= end) break;
        acc = 0.f; wacc = 0.f;
        gid++;
        bnd = g_eoff[gid + 1];
    }
}

// ============================================================================
// Output kernel: gather node_out rows (fp32); block 0 computes the loss.
// ============================================================================
__global__ void out_kernel(float* __restrict__ out, int G, int lossIdx) {
    int g = blockIdx.x;
    int t = threadIdx.x;
    if (g < G)
        out[g * DF + t] = g_h[(size_t)g_nid[g] * DF + t];
    if (g == 0) {
        __shared__ float red[128];
        float term = 0.f;
        if (t < G) {
            float w = g_wsum[t];
            term = (w != 0.f) ? (g_esum[t] / w) : 0.f;
        }
        red[t] = term;
        __syncthreads();
        #pragma unroll
        for (int s = 64; s; s >>= 1) {
            if (t < s) red[t] += red[t + s];
            __syncthreads();
        }
        if (t == 0) out[lossIdx] = red[0] / (float)G;
    }
}

// ============================================================================
extern "C" void kernel_launch(void* const* d_in, const int* in_sizes, int n_in,
                              void* d_out, int out_size) {
    const float* nodes     = (const float*)d_in[0];
    const float* edges     = (const float*)d_in[1];
    const int*   senders   = (const int*)d_in[2];
    const int*   receivers = (const int*)d_in[3];
    const int*   n_node    = (const int*)d_in[4];
    const int*   n_edge    = (const int*)d_in[5];
    const float* W1        = (const float*)d_in[6];
    const float* b1        = (const float*)d_in[7];
    const float* W2        = (const float*)d_in[8];
    const float* b2        = (const float*)d_in[9];
    float* out = (float*)d_out;

    int M = in_sizes[0] / DF;
    int E = in_sizes[2];
    int G = in_sizes[4];
    int mtiles = (M + 127) / 128;

    void *pnAh, *pnAl, *pW1h, *pW1l, *pW2h, *pW2l, *pth, *ptl, *ph, *phb;
    cudaGetSymbolAddress(&pnAh, g_nAh); cudaGetSymbolAddress(&pnAl, g_nAl);
    cudaGetSymbolAddress(&pW1h, g_W1h); cudaGetSymbolAddress(&pW1l, g_W1l);
    cudaGetSymbolAddress(&pW2h, g_W2h); cudaGetSymbolAddress(&pW2l, g_W2l);
    cudaGetSymbolAddress(&pth, g_th);   cudaGetSymbolAddress(&ptl, g_tl);
    cudaGetSymbolAddress(&ph, g_h);     cudaGetSymbolAddress(&phb, g_hb);

    prefix_kernel<<<1, 128>>>(n_node, n_edge, G);

    split_kernel<<<(M * DF + 255) / 256, 256>>>(
        nodes, (__nv_bfloat16*)pnAh, (__nv_bfloat16*)pnAl, M * DF);
    tsplit_kernel<<<(DF * DH + 255) / 256, 256>>>(
        W1, (__nv_bfloat16*)pW1h, (__nv_bfloat16*)pW1l, DF, DH);
    tsplit_kernel<<<(DH * DF + 255) / 256, 256>>>(
        W2, (__nv_bfloat16*)pW2h, (__nv_bfloat16*)pW2l, DH, DF);

    // GEMM1: nodes[M,128] @ W1 -> relu -> th/tl [M,512]
    gemm_mma<<<dim3(DH / 128, mtiles), 256>>>(
        (const __nv_bfloat16*)pnAh, (const __nv_bfloat16*)pnAl,
        (const __nv_bfloat16*)pW1h, (const __nv_bfloat16*)pW1l,
        b1, nullptr, (__nv_bfloat16*)pth, (__nv_bfloat16*)ptl,
        M, DH, DF, 1);
    // GEMM2: th/tl[M,512] @ W2 -> g_h fp32 + g_hb mirror [M,128]
    gemm_mma<<<dim3(DF / 128, mtiles), 256>>>(
        (const __nv_bfloat16*)pth, (const __nv_bfloat16*)ptl,
        (const __nv_bfloat16*)pW2h, (const __nv_bfloat16*)pW2l,
        b2, (float*)ph, (__nv_bfloat16*)phb, nullptr,
        M, DF, DH, 0);

    int eblocks = (E + EPW * 8 - 1) / (EPW * 8);
    edge_kernel<<<eblocks, 256>>>(edges, senders, receivers, E, G);

    out_kernel<<<G, 128>>>(out, G, out_size - 1);
}

// round 17
// speedup vs baseline: 1.9634x; 1.9634x over previous
#include <cuda_runtime.h>
#include <cuda_bf16.h>
#include <cstdint>

#define DF 128          // feature dim
#define DH 512          // hidden dim
#define MAXN 10000      // nodes
#define MAXG 128        // >= n_graphs (100)
#define EPW 32          // edges per warp strip (R8 known-good)

// ---------------- static device scratch (no allocations allowed) ------------
__device__ __nv_bfloat16 g_nAh[MAXN * DF], g_nAl[MAXN * DF]; // nodes hi/lo
__device__ __nv_bfloat16 g_W1h[DH * DF],  g_W1l[DH * DF];    // W1^T [512x128]
__device__ __nv_bfloat16 g_W2h[DF * DH],  g_W2l[DF * DH];    // W2^T [128x512]
__device__ __nv_bfloat16 g_th[MAXN * DH], g_tl[MAXN * DH];   // relu layer hi/lo
__device__ float         g_h[MAXN * DF];                     // final h (fp32)
__device__ __nv_bfloat16 g_hb[MAXN * DF];                    // bf16 mirror (=hi)
__device__ float g_wsum[MAXG];
__device__ float g_esum[MAXG];
__device__ int   g_eoff[MAXG + 1];
__device__ int   g_nid[MAXG];

__device__ __forceinline__ uint32_t smem_u32(const void* p) {
    uint32_t a;
    asm("{ .reg .u64 t; cvta.to.shared.u64 t, %1; cvt.u32.u64 %0, t; }"
        : "=r"(a) : "l"(p));
    return a;
}
#define SW128(x) ((x) ^ (((x) >> 3) & 0x70))

__device__ __forceinline__ void ldsm_x4(uint32_t& r0, uint32_t& r1,
                                        uint32_t& r2, uint32_t& r3, uint32_t a) {
    asm volatile("ldmatrix.sync.aligned.m8n8.x4.shared.b16 {%0,%1,%2,%3}, [%4];"
                 : "=r"(r0), "=r"(r1), "=r"(r2), "=r"(r3) : "r"(a));
}
__device__ __forceinline__ void mma_bf16(float* d, const uint32_t* a,
                                         const uint32_t* b) {
    asm volatile(
        "mma.sync.aligned.m16n8k16.row.col.f32.bf16.bf16.f32 "
        "{%0,%1,%2,%3}, {%4,%5,%6,%7}, {%8,%9}, {%0,%1,%2,%3};"
        : "+f"(d[0]), "+f"(d[1]), "+f"(d[2]), "+f"(d[3])
        : "r"(a[0]), "r"(a[1]), "r"(a[2]), "r"(a[3]), "r"(b[0]), "r"(b[1]));
}

// ============================================================================
// Kernel 0: prefix sums + zero accumulators (runs every replay)
// ============================================================================
__global__ void prefix_kernel(const int* __restrict__ n_node,
                              const int* __restrict__ n_edge, int G) {
    int t = threadIdx.x;
    if (t < MAXG) { g_wsum[t] = 0.f; g_esum[t] = 0.f; }
    if (t == 0) {
        int ea = 0, na = 0;
        g_eoff[0] = 0;
        for (int g = 0; g < G; g++) {
            ea += n_edge[g]; g_eoff[g + 1] = ea;
            na += n_node[g]; g_nid[g] = na - 1;
        }
    }
}

// ============================================================================
// Split fp32 -> bf16 hi/lo (same layout)
// ============================================================================
__global__ void split_kernel(const float* __restrict__ in,
                             __nv_bfloat16* __restrict__ hi,
                             __nv_bfloat16* __restrict__ lo, int n) {
    int i = blockIdx.x * 256 + threadIdx.x;
    if (i < n) {
        float a = in[i];
        __nv_bfloat16 h = __float2bfloat16(a);
        hi[i] = h;
        lo[i] = __float2bfloat16(a - __bfloat162float(h));
    }
}

// ============================================================================
// Transpose + split: W [Kd x Nd] fp32 row-major -> T hi/lo [Nd x Kd] bf16
// ============================================================================
__global__ void tsplit_kernel(const float* __restrict__ W,
                              __nv_bfloat16* __restrict__ Th,
                              __nv_bfloat16* __restrict__ Tl, int Kd, int Nd) {
    int i = blockIdx.x * 256 + threadIdx.x;
    if (i < Kd * Nd) {
        int k = i / Nd, n = i % Nd;
        float a = W[i];
        __nv_bfloat16 h = __float2bfloat16(a);
        Th[(size_t)n * Kd + k] = h;
        Tl[(size_t)n * Kd + k] = __float2bfloat16(a - __bfloat162float(h));
    }
}

// ============================================================================
// bf16 mma.sync GEMM v2: 3-pass hi/lo (hh, h*lo, lo*h), single fill per k0.
// A [M x K] row-major bf16 pair; B [N x K] row-major bf16 pair (W^T).
// CTA tile 64(M) x 128(N), 256 thr = 8 warps in 2(m) x 4(n); warp tile 32x32.
// BK=64 (128B rows, SW128). All 4 tiles resident (48KB): Ah,Al 8KB; Bh,Bl 16KB.
// ============================================================================
#define SAH 0
#define SAL 8192
#define SBH 16384
#define SBL 32768

__global__ __launch_bounds__(256)
void gemm_mma(const __nv_bfloat16* __restrict__ Ah, const __nv_bfloat16* __restrict__ Al,
              const __nv_bfloat16* __restrict__ Bh, const __nv_bfloat16* __restrict__ Bl,
              const float* __restrict__ bias, float* __restrict__ Cf,
              __nv_bfloat16* __restrict__ Chi, __nv_bfloat16* __restrict__ Clo,
              int M, int N, int K, int doRelu) {
    __shared__ __align__(1024) uint8_t sMem[49152];

    int tid = threadIdx.x, lane = tid & 31, wid = tid >> 5;
    int warp_m = wid & 1;          // 2 m-slices of 32 rows
    int warp_n = wid >> 1;         // 4 n-slices of 32 cols
    int row0 = blockIdx.y * 64, col0 = blockIdx.x * 128;
    uint32_t sb = smem_u32(sMem);
    int r8 = lane & 7, sel = lane >> 3;

    float acc[2][4][4];
    #pragma unroll
    for (int i = 0; i < 2; i++)
        #pragma unroll
        for (int j = 0; j < 4; j++)
            #pragma unroll
            for (int q = 0; q < 4; q++) acc[i][j][q] = 0.f;

    #pragma unroll 1
    for (int k0 = 0; k0 < K; k0 += 64) {
        // ---- fill all 4 tiles once per k0 ----
        for (int i = tid; i < 64 * 8; i += 256) {       // Ah, Al: 64 rows x 8 c
            int r = i >> 3, c = i & 7;
            int gr = row0 + r;
            uint4 vh = make_uint4(0, 0, 0, 0), vl = make_uint4(0, 0, 0, 0);
            if (gr < M) {
                vh = *(const uint4*)(Ah + (size_t)gr * K + k0 + c * 8);
                vl = *(const uint4*)(Al + (size_t)gr * K + k0 + c * 8);
            }
            uint32_t off = SW128(r * 128 + c * 16);
            *(uint4*)(sMem + SAH + off) = vh;
            *(uint4*)(sMem + SAL + off) = vl;
        }
        for (int i = tid; i < 128 * 8; i += 256) {      // Bh, Bl: 128 rows x 8 c
            int r = i >> 3, c = i & 7;
            uint4 vh = *(const uint4*)(Bh + (size_t)(col0 + r) * K + k0 + c * 8);
            uint4 vl = *(const uint4*)(Bl + (size_t)(col0 + r) * K + k0 + c * 8);
            uint32_t off = SW128(r * 128 + c * 16);
            *(uint4*)(sMem + SBH + off) = vh;
            *(uint4*)(sMem + SBL + off) = vl;
        }
        __syncthreads();

        // ---- 3 passes against resident tiles: (h,h), (h,l), (l,h) ----
        #pragma unroll
        for (int pass = 0; pass < 3; pass++) {
            uint32_t sAa = sb + ((pass == 2) ? SAL : SAH);
            uint32_t sBa = sb + ((pass == 1) ? SBL : SBH);
            #pragma unroll
            for (int kk = 0; kk < 4; kk++) {     // 4 x k16
                int kb = kk * 32;
                uint32_t a[2][4], b[4][2];
                #pragma unroll
                for (int mi = 0; mi < 2; mi++) {
                    int mr = warp_m * 32 + mi * 16 + (sel & 1) * 8 + r8;
                    uint32_t ad = sAa + SW128(mr * 128 + kb + (sel >> 1) * 16);
                    ldsm_x4(a[mi][0], a[mi][1], a[mi][2], a[mi][3], ad);
                }
                #pragma unroll
                for (int nj = 0; nj < 2; nj++) {
                    int nr = warp_n * 32 + nj * 16 + (sel >> 1) * 8 + r8;
                    uint32_t bd = sBa + SW128(nr * 128 + kb + (sel & 1) * 16);
                    ldsm_x4(b[nj * 2][0], b[nj * 2][1],
                            b[nj * 2 + 1][0], b[nj * 2 + 1][1], bd);
                }
                #pragma unroll
                for (int mi = 0; mi < 2; mi++)
                    #pragma unroll
                    for (int ni = 0; ni < 4; ni++)
                        mma_bf16(acc[mi][ni], a[mi], b[ni]);
            }
        }
        __syncthreads();
    }

    // ---- epilogue: frag rows/cols; bias + relu; stores ----
    int tr = lane >> 2, tc = (lane & 3) * 2;
    #pragma unroll
    for (int mi = 0; mi < 2; mi++) {
        int ra = row0 + warp_m * 32 + mi * 16 + tr;
        int rb = ra + 8;
        #pragma unroll
        for (int ni = 0; ni < 4; ni++) {
            int col = col0 + warp_n * 32 + ni * 8 + tc;
            float bb0 = __ldg(bias + col), bb1 = __ldg(bias + col + 1);
            float v0 = acc[mi][ni][0] + bb0, v1 = acc[mi][ni][1] + bb1;
            float v2 = acc[mi][ni][2] + bb0, v3 = acc[mi][ni][3] + bb1;
            if (doRelu) {
                v0 = fmaxf(v0, 0.f); v1 = fmaxf(v1, 0.f);
                v2 = fmaxf(v2, 0.f); v3 = fmaxf(v3, 0.f);
            }
            if (ra < M) {
                size_t o = (size_t)ra * N + col;
                if (Cf) *(float2*)(Cf + o) = make_float2(v0, v1);
                __nv_bfloat162 h2 = __floats2bfloat162_rn(v0, v1);
                *(unsigned*)(Chi + o) = *(unsigned*)&h2;
                if (Clo) {
                    __nv_bfloat162 l2 = __floats2bfloat162_rn(
                        v0 - __bfloat162float(h2.x), v1 - __bfloat162float(h2.y));
                    *(unsigned*)(Clo + o) = *(unsigned*)&l2;
                }
            }
            if (rb < M) {
                size_t o = (size_t)rb * N + col;
                if (Cf) *(float2*)(Cf + o) = make_float2(v2, v3);
                __nv_bfloat162 h2 = __floats2bfloat162_rn(v2, v3);
                *(unsigned*)(Chi + o) = *(unsigned*)&h2;
                if (Clo) {
                    __nv_bfloat162 l2 = __floats2bfloat162_rn(
                        v2 - __bfloat162float(h2.x), v3 - __bfloat162float(h2.y));
                    *(unsigned*)(Clo + o) = *(unsigned*)&l2;
                }
            }
        }
    }
}

// ============================================================================
// Edge kernel (R8 known-good, 40us): one warp per strip of EPW edges.
// ============================================================================
__global__ __launch_bounds__(256)
void edge_kernel(const float* __restrict__ ew,
                 const int* __restrict__ snd, const int* __restrict__ rcv,
                 int E, int G) {
    int lane = threadIdx.x & 31;
    int wl = threadIdx.x >> 5;
    int warp = blockIdx.x * 8 + wl;
    int base = warp * EPW;
    if (base >= E) return;
    int end = min(base + EPW, E);

    int lo = 0, hi = G;
    while (hi - lo > 1) {
        int mid = (lo + hi) >> 1;
        if (g_eoff[mid] <= base) lo = mid; else hi = mid;
    }
    int gid = lo;
    int bnd = g_eoff[gid + 1];

    const __nv_bfloat16* __restrict__ hb = g_hb;
    float acc = 0.f, wacc = 0.f;
    int e = base;
    for (;;) {
        int seg = min(end, bnd);
        #pragma unroll 4
        for (; e < seg; e++) {
            int s = __ldg(snd + e);
            int r = __ldg(rcv + e);
            float w = __ldg(ew + e);
            uint2 av = *(const uint2*)(hb + (size_t)s * DF + lane * 4);
            uint2 bv = *(const uint2*)(hb + (size_t)r * DF + lane * 4);
            unsigned d0, d1;
            asm("sub.rn.bf16x2 %0, %1, %2;" : "=r"(d0) : "r"(av.x), "r"(bv.x));
            asm("sub.rn.bf16x2 %0, %1, %2;" : "=r"(d1) : "r"(av.y), "r"(bv.y));
            float f0 = __uint_as_float(d0 << 16);
            float f1 = __uint_as_float(d0 & 0xFFFF0000u);
            float f2 = __uint_as_float(d1 << 16);
            float f3 = __uint_as_float(d1 & 0xFFFF0000u);
            float t = f0 * f0;
            t = fmaf(f1, f1, t);
            t = fmaf(f2, f2, t);
            t = fmaf(f3, f3, t);
            acc = fmaf(w, t, acc);
            if (lane == 0) wacc += w;
        }
        float v = acc;
        #pragma unroll
        for (int off = 16; off; off >>= 1)
            v += __shfl_xor_sync(0xffffffffu, v, off);
        if (lane == 0) {
            atomicAdd(&g_esum[gid], v);
            atomicAdd(&g_wsum[gid], wacc);
        }
        if (e >= end) break;
        acc = 0.f; wacc = 0.f;
        gid++;
        bnd = g_eoff[gid + 1];
    }
}

// ============================================================================
// Output kernel: gather node_out rows (fp32); block 0 computes the loss.
// ============================================================================
__global__ void out_kernel(float* __restrict__ out, int G, int lossIdx) {
    int g = blockIdx.x;
    int t = threadIdx.x;
    if (g < G)
        out[g * DF + t] = g_h[(size_t)g_nid[g] * DF + t];
    if (g == 0) {
        __shared__ float red[128];
        float term = 0.f;
        if (t < G) {
            float w = g_wsum[t];
            term = (w != 0.f) ? (g_esum[t] / w) : 0.f;
        }
        red[t] = term;
        __syncthreads();
        #pragma unroll
        for (int s = 64; s; s >>= 1) {
            if (t < s) red[t] += red[t + s];
            __syncthreads();
        }
        if (t == 0) out[lossIdx] = red[0] / (float)G;
    }
}

// ============================================================================
extern "C" void kernel_launch(void* const* d_in, const int* in_sizes, int n_in,
                              void* d_out, int out_size) {
    const float* nodes     = (const float*)d_in[0];
    const float* edges     = (const float*)d_in[1];
    const int*   senders   = (const int*)d_in[2];
    const int*   receivers = (const int*)d_in[3];
    const int*   n_node    = (const int*)d_in[4];
    const int*   n_edge    = (const int*)d_in[5];
    const float* W1        = (const float*)d_in[6];
    const float* b1        = (const float*)d_in[7];
    const float* W2        = (const float*)d_in[8];
    const float* b2        = (const float*)d_in[9];
    float* out = (float*)d_out;

    int M = in_sizes[0] / DF;
    int E = in_sizes[2];
    int G = in_sizes[4];
    int mtiles = (M + 63) / 64;

    void *pnAh, *pnAl, *pW1h, *pW1l, *pW2h, *pW2l, *pth, *ptl, *ph, *phb;
    cudaGetSymbolAddress(&pnAh, g_nAh); cudaGetSymbolAddress(&pnAl, g_nAl);
    cudaGetSymbolAddress(&pW1h, g_W1h); cudaGetSymbolAddress(&pW1l, g_W1l);
    cudaGetSymbolAddress(&pW2h, g_W2h); cudaGetSymbolAddress(&pW2l, g_W2l);
    cudaGetSymbolAddress(&pth, g_th);   cudaGetSymbolAddress(&ptl, g_tl);
    cudaGetSymbolAddress(&ph, g_h);     cudaGetSymbolAddress(&phb, g_hb);

    prefix_kernel<<<1, 128>>>(n_node, n_edge, G);

    split_kernel<<<(M * DF + 255) / 256, 256>>>(
        nodes, (__nv_bfloat16*)pnAh, (__nv_bfloat16*)pnAl, M * DF);
    tsplit_kernel<<<(DF * DH + 255) / 256, 256>>>(
        W1, (__nv_bfloat16*)pW1h, (__nv_bfloat16*)pW1l, DF, DH);
    tsplit_kernel<<<(DH * DF + 255) / 256, 256>>>(
        W2, (__nv_bfloat16*)pW2h, (__nv_bfloat16*)pW2l, DH, DF);

    // GEMM1: nodes[M,128] @ W1 -> relu -> th/tl [M,512]   grid (4, 157)
    gemm_mma<<<dim3(DH / 128, mtiles), 256>>>(
        (const __nv_bfloat16*)pnAh, (const __nv_bfloat16*)pnAl,
        (const __nv_bfloat16*)pW1h, (const __nv_bfloat16*)pW1l,
        b1, nullptr, (__nv_bfloat16*)pth, (__nv_bfloat16*)ptl,
        M, DH, DF, 1);
    // GEMM2: th/tl[M,512] @ W2 -> g_h fp32 + g_hb mirror  grid (1, 157)
    gemm_mma<<<dim3(DF / 128, mtiles), 256>>>(
        (const __nv_bfloat16*)pth, (const __nv_bfloat16*)ptl,
        (const __nv_bfloat16*)pW2h, (const __nv_bfloat16*)pW2l,
        b2, (float*)ph, (__nv_bfloat16*)phb, nullptr,
        M, DF, DH, 0);

    int eblocks = (E + EPW * 8 - 1) / (EPW * 8);
    edge_kernel<<<eblocks, 256>>>(edges, senders, receivers, E, G);

    out_kernel<<<G, 128>>>(out, G, out_size - 1);
}